// round 10
// baseline (speedup 1.0000x reference)
#include <cuda_runtime.h>
#include <math.h>

// Problem shapes (fixed by the dataset)
#define B  32
#define C  512
#define D  4096
#define H  128        // hidden
#define NROWS (B * C) // 16384

// Pool kernel tiling
#define PR    128            // rows per block (= adder threads)
#define PCH   32             // columns per chunk
#define NCH   (D / PCH)      // 128 chunks
#define PTHREADS 384         // 4 adder warps + 8 loader warps
#define NLOAD (PTHREADS - PR)        // 256 loader threads
#define F4PC  (PR * PCH / 4)         // float4 per chunk = 1024
#define F4PT  (F4PC / NLOAD)         // float4 per loader thread = 4

// Scratch (no cudaMalloc allowed)
__device__ float g_pooled[B * C];
__device__ int   g_ord[B * C];

// ---------------------------------------------------------------------------
// Bit-faithful XLA-CPU vectorized expf. PROVEN: rel_err == 0.0. DO NOT MODIFY.
// ---------------------------------------------------------------------------
__device__ __forceinline__ float xla_cpu_expf(float x) {
    const float exp_hi = 88.3762626647950f;
    const float exp_lo = -88.3762626647949f;
    const float LOG2EF = 1.44269504088896341f;
    const float C1 = 0.693359375f;
    const float C2 = -2.12194440e-4f;
    const float p0 = 1.9875691500e-4f;
    const float p1 = 1.3981999507e-3f;
    const float p2 = 8.3334519073e-3f;
    const float p3 = 4.1665795894e-2f;
    const float p4 = 1.6666665459e-1f;
    const float p5 = 5.0000001201e-1f;

    x = fminf(fmaxf(x, exp_lo), exp_hi);

    float fx = __fadd_rn(__fmul_rn(x, LOG2EF), 0.5f);
    fx = floorf(fx);

    float tmp = __fmul_rn(fx, C1);
    float z   = __fmul_rn(fx, C2);
    x = __fsub_rn(x, tmp);
    x = __fsub_rn(x, z);
    z = __fmul_rn(x, x);

    float y = p0;
    y = __fadd_rn(__fmul_rn(y, x), p1);
    y = __fadd_rn(__fmul_rn(y, x), p2);
    y = __fadd_rn(__fmul_rn(y, x), p3);
    y = __fadd_rn(__fmul_rn(y, x), p4);
    y = __fadd_rn(__fmul_rn(y, x), p5);
    y = __fadd_rn(__fmul_rn(y, z), x);
    y = __fadd_rn(y, 1.0f);

    int n = (int)fx;
    y = __fmul_rn(y, __int_as_float((n + 127) << 23));
    return y;
}

// ---------------------------------------------------------------------------
// Kernel A: pooled[row] = (strict sequential fp32 sum over d) * (1/4096).
// SAME ADDITION ORDER as round 8 (bit-exact) — scheduling only:
//   warps 0-3  (tid <128): adders — LDS + serial FADD chain with an 8-deep
//                          rolling register lookahead (hides 29-cyc LDS lat)
//   warps 4-11 (tid>=128): loaders — LDG float4 (coalesced) -> transposed STS
//                          into a 2-slot smem ring; double-buffered registers
//                          give each chunk's LDGs a full iteration of latency.
// chunk ch lives in slot[ch&1]; iter ch: adders eat slot[ch&1], loaders STS
// chunk ch+1 into slot[(ch+1)&1] and issue LDG for chunk ch+2.
// Banks: adder LDS (i+tid)%32 conflict-free; loader STS (4*c4+j+r)%32
// covers 0..31 exactly once per warp — conflict-free.
// ---------------------------------------------------------------------------
__global__ void __launch_bounds__(PTHREADS) pool_kernel(const float* __restrict__ x) {
    __shared__ float tile[2][PCH][PR + 1];   // 2 * 32 * 129 * 4B = 33 KB

    const int tid  = threadIdx.x;
    const int base = blockIdx.x * PR;
    const float4* __restrict__ x4 = reinterpret_cast<const float4*>(x);

    if (tid >= PR) {
        // ------------------ loader path ------------------
        const int lt = tid - PR;            // 0..255
        float4 buf[2][F4PT];

        // indices for this thread's 4 float4s (fixed across chunks)
        int rr[F4PT], cc4[F4PT];
#pragma unroll
        for (int it = 0; it < F4PT; ++it) {
            const int g = lt + it * NLOAD;  // 0..1023
            rr[it]  = g >> 3;               // row in block
            cc4[it] = g & 7;                // float4 within chunk
        }

        // prologue: chunk0 -> buf[0] -> slot0 ; chunk1 -> buf[1]
#pragma unroll
        for (int it = 0; it < F4PT; ++it)
            buf[0][it] = x4[(size_t)(base + rr[it]) * (D / 4) + cc4[it]];
#pragma unroll
        for (int it = 0; it < F4PT; ++it) {
            const int c = cc4[it] * 4, r = rr[it];
            tile[0][c + 0][r] = buf[0][it].x;
            tile[0][c + 1][r] = buf[0][it].y;
            tile[0][c + 2][r] = buf[0][it].z;
            tile[0][c + 3][r] = buf[0][it].w;
        }
#pragma unroll
        for (int it = 0; it < F4PT; ++it)
            buf[1][it] = x4[(size_t)(base + rr[it]) * (D / 4) + 8 + cc4[it]];
        __syncthreads();

        for (int ch = 0; ch < NCH; ++ch) {
            // issue LDG for chunk ch+2 first (consumed next iteration)
            if (ch + 2 < NCH) {
#pragma unroll
                for (int it = 0; it < F4PT; ++it)
                    buf[ch & 1][it] =
                        x4[(size_t)(base + rr[it]) * (D / 4)
                           + (size_t)(ch + 2) * (PCH / 4) + cc4[it]];
            }
            // stage chunk ch+1 (loaded last iteration) into its slot
            if (ch + 1 < NCH) {
                const int s = (ch + 1) & 1;
#pragma unroll
                for (int it = 0; it < F4PT; ++it) {
                    const int c = cc4[it] * 4, r = rr[it];
                    tile[s][c + 0][r] = buf[(ch + 1) & 1][it].x;
                    tile[s][c + 1][r] = buf[(ch + 1) & 1][it].y;
                    tile[s][c + 2][r] = buf[(ch + 1) & 1][it].z;
                    tile[s][c + 3][r] = buf[(ch + 1) & 1][it].w;
                }
            }
            __syncthreads();
        }
    } else {
        // ------------------ adder path ------------------
        __syncthreads();                    // matches loader prologue sync

        float acc = 0.f;
        for (int ch = 0; ch < NCH; ++ch) {
            const int s = ch & 1;
            // rolling 8-deep lookahead: LDS issued 8 adds (32 cyc) early
            float v[8];
#pragma unroll
            for (int j = 0; j < 8; ++j) v[j] = tile[s][j][tid];
#pragma unroll
            for (int i = 0; i < PCH; ++i) {
                acc = __fadd_rn(acc, v[i & 7]);
                if (i + 8 < PCH) v[i & 7] = tile[s][i + 8][tid];
            }
            __syncthreads();
        }
        g_pooled[base + tid] = __fmul_rn(acc, (1.0f / (float)D));
    }
}

// ---------------------------------------------------------------------------
// Kernel B: per batch-item (grid = 32, block = 512), fp32 throughout.
// PROVEN bit-exact (rel_err==0.0). DO NOT MODIFY ARITHMETIC.
// ---------------------------------------------------------------------------
__global__ void __launch_bounds__(512) mlp_sort_kernel(
    const float* __restrict__ W1, const float* __restrict__ b1,
    const float* __restrict__ W2, const float* __restrict__ b2) {
    const int b   = blockIdx.x;
    const int tid = threadIdx.x;

    __shared__ float ps[C];
    __shared__ float hs[H];
    __shared__ float ss[C];
    __shared__ int   si[C];

    ps[tid] = g_pooled[b * C + tid];
    __syncthreads();

    if (tid < H) {
        const float* __restrict__ w = W1 + tid * C;
        float acc = 0.f;
        for (int k = 0; k < C; k++) acc = fmaf(w[k], ps[k], acc);
        acc = __fadd_rn(acc, b1[tid]);
        hs[tid] = (acc >= 0.f) ? acc : __fmul_rn(0.01f, acc);
    }
    __syncthreads();

    {
        const float* __restrict__ w = W2 + tid * H;
        float acc = 0.f;
        for (int k = 0; k < H; k++) acc = fmaf(w[k], hs[k], acc);
        acc = __fadd_rn(acc, b2[tid]);
        float e = xla_cpu_expf(-acc);
        ss[tid] = __fdiv_rn(1.0f, __fadd_rn(1.0f, e));
        si[tid] = tid;
    }
    __syncthreads();

    // Bitonic sort, 512 elems, key = (score desc, idx asc).
    for (int k = 2; k <= C; k <<= 1) {
        for (int j = k >> 1; j > 0; j >>= 1) {
            const int i   = tid;
            const int ixj = i ^ j;
            if (ixj > i) {
                const float a_s = ss[i],  b_s = ss[ixj];
                const int   a_i = si[i],  b_i = si[ixj];
                const bool b_precedes_a = (b_s > a_s) || (b_s == a_s && b_i < a_i);
                const bool a_precedes_b = (a_s > b_s) || (a_s == b_s && a_i < b_i);
                const bool up = ((i & k) == 0);
                const bool do_swap = up ? b_precedes_a : a_precedes_b;
                if (do_swap) {
                    ss[i] = b_s; ss[ixj] = a_s;
                    si[i] = b_i; si[ixj] = a_i;
                }
            }
            __syncthreads();
        }
    }

    g_ord[b * C + tid] = si[tid];
}

// ---------------------------------------------------------------------------
// Kernel C: out[b,c,:] = x[b,c,:] + x[b, ord[b][c], :]
// b-major grid: concurrent blocks share one 8 MiB batch slice (<< 126 MB L2)
// so the gathered second read hits L2, not DRAM.
// ---------------------------------------------------------------------------
__global__ void __launch_bounds__(256) shuffle_add_kernel(
    const float* __restrict__ x, float* __restrict__ out) {
    const int row = blockIdx.x;          // b*512 + c
    const int b   = row >> 9;
    const int src = g_ord[row];

    const float4* __restrict__ xa =
        reinterpret_cast<const float4*>(x + (size_t)row * D);
    const float4* __restrict__ xb =
        reinterpret_cast<const float4*>(x + ((size_t)(b << 9) + src) * D);
    float4* __restrict__ o = reinterpret_cast<float4*>(out + (size_t)row * D);

#pragma unroll 4
    for (int i = threadIdx.x; i < D / 4; i += 256) {
        float4 a = xa[i];
        float4 g = xb[i];
        a.x += g.x; a.y += g.y; a.z += g.z; a.w += g.w;
        o[i] = a;
    }
}

// ---------------------------------------------------------------------------
extern "C" void kernel_launch(void* const* d_in, const int* in_sizes, int n_in,
                              void* d_out, int out_size) {
    const float* x  = (const float*)d_in[0];
    const float* W1 = (const float*)d_in[1];
    const float* b1 = (const float*)d_in[2];
    const float* W2 = (const float*)d_in[3];
    const float* b2 = (const float*)d_in[4];
    float* out = (float*)d_out;

    pool_kernel<<<NROWS / PR, PTHREADS>>>(x);
    mlp_sort_kernel<<<B, 512>>>(W1, b1, W2, b2);
    shuffle_add_kernel<<<NROWS, 256>>>(x, out);
}

// round 11
// speedup vs baseline: 2.2432x; 2.2432x over previous
#include <cuda_runtime.h>
#include <math.h>
#include <stdint.h>

// Problem shapes (fixed by the dataset)
#define B  32
#define C  512
#define D  4096
#define H  128        // hidden
#define NROWS (B * C) // 16384

// Pool kernel: cp.async pipelined staging
#define PR      128          // rows per block == threads per block
#define PCH     16           // columns per chunk
#define NCH     (D / PCH)    // 256 chunks
#define NSTAGE  4            // smem ring depth (power of 2)
#define SSTRIDE 20           // floats per row in a stage (16 + 4 pad; 80B, 16B-aligned)

// Scratch (no cudaMalloc allowed)
__device__ float g_pooled[B * C];
__device__ int   g_ord[B * C];

// ---------------------------------------------------------------------------
// Bit-faithful XLA-CPU vectorized expf. PROVEN: rel_err == 0.0. DO NOT MODIFY.
// ---------------------------------------------------------------------------
__device__ __forceinline__ float xla_cpu_expf(float x) {
    const float exp_hi = 88.3762626647950f;
    const float exp_lo = -88.3762626647949f;
    const float LOG2EF = 1.44269504088896341f;
    const float C1 = 0.693359375f;
    const float C2 = -2.12194440e-4f;
    const float p0 = 1.9875691500e-4f;
    const float p1 = 1.3981999507e-3f;
    const float p2 = 8.3334519073e-3f;
    const float p3 = 4.1665795894e-2f;
    const float p4 = 1.6666665459e-1f;
    const float p5 = 5.0000001201e-1f;

    x = fminf(fmaxf(x, exp_lo), exp_hi);

    float fx = __fadd_rn(__fmul_rn(x, LOG2EF), 0.5f);
    fx = floorf(fx);

    float tmp = __fmul_rn(fx, C1);
    float z   = __fmul_rn(fx, C2);
    x = __fsub_rn(x, tmp);
    x = __fsub_rn(x, z);
    z = __fmul_rn(x, x);

    float y = p0;
    y = __fadd_rn(__fmul_rn(y, x), p1);
    y = __fadd_rn(__fmul_rn(y, x), p2);
    y = __fadd_rn(__fmul_rn(y, x), p3);
    y = __fadd_rn(__fmul_rn(y, x), p4);
    y = __fadd_rn(__fmul_rn(y, x), p5);
    y = __fadd_rn(__fmul_rn(y, z), x);
    y = __fadd_rn(y, 1.0f);

    int n = (int)fx;
    y = __fmul_rn(y, __int_as_float((n + 127) << 23));
    return y;
}

// ---------------------------------------------------------------------------
// Kernel A: pooled[row] = (strict sequential fp32 sum over d) * (1/4096).
// IDENTICAL addition order to round 8 (bit-exact). Scheduling: 4-stage
// cp.async ring. Each thread owns one row (tid), consumes 16 columns per
// chunk via 4× LDS.128, adding components in strict column order.
// cp.async: per stage each thread copies 4× 16B, coalesced in groups of 4
// lanes per row-segment; hardware-tracked (no register staging, no spills).
// Group algebra: prologue commits stages 0..2; every iteration commits
// exactly one group (empty at tail), so at iteration ch exactly ch+3 groups
// are committed and `wait_group 2` guarantees chunk ch is resident.
// ---------------------------------------------------------------------------
__global__ void __launch_bounds__(PR) pool_kernel(const float* __restrict__ x) {
    __shared__ float ring[NSTAGE][PR * SSTRIDE];   // 4 * 128*20*4B = 40 KB

    const int tid  = threadIdx.x;
    const int base = blockIdx.x * PR;
    const float4* __restrict__ x4 = reinterpret_cast<const float4*>(x);

    // Issue one stage: 128 rows x 4 float4 = 512 copies, 4 per thread.
    // g = tid + it*PR: row = g>>2, c4 = g&3 (4 consecutive lanes per 64B seg).
#define ISSUE_STAGE(CH)                                                        \
    do {                                                                       \
        const int _s = (CH) & (NSTAGE - 1);                                    \
        _Pragma("unroll")                                                      \
        for (int _it = 0; _it < 4; ++_it) {                                    \
            const int _g  = tid + _it * PR;                                    \
            const int _r  = _g >> 2;                                           \
            const int _c4 = _g & 3;                                            \
            const float4* _src = &x4[(size_t)(base + _r) * (D / 4)             \
                                     + (size_t)(CH) * (PCH / 4) + _c4];        \
            uint32_t _dst = (uint32_t)__cvta_generic_to_shared(                \
                &ring[_s][_r * SSTRIDE + _c4 * 4]);                            \
            asm volatile("cp.async.cg.shared.global [%0], [%1], 16;"           \
                         :: "r"(_dst), "l"(_src) : "memory");                  \
        }                                                                      \
        asm volatile("cp.async.commit_group;" ::: "memory");                   \
    } while (0)

    ISSUE_STAGE(0);
    ISSUE_STAGE(1);
    ISSUE_STAGE(2);

    float acc = 0.f;
    for (int ch = 0; ch < NCH; ++ch) {
        asm volatile("cp.async.wait_group 2;" ::: "memory");
        __syncthreads();   // make other threads' cp.async data visible;
                           // also fences prior iteration's reads before the
                           // overwrite of slot (ch+3)&3 below.

        // Refill first (overlaps the add chain below).
        if (ch + 3 < NCH) {
            ISSUE_STAGE(ch + 3);
        } else {
            asm volatile("cp.async.commit_group;" ::: "memory"); // empty group
        }

        // Strict sequential accumulation over this chunk's 16 columns.
        const int s = ch & (NSTAGE - 1);
        const float4* rowp =
            reinterpret_cast<const float4*>(&ring[s][tid * SSTRIDE]);
#pragma unroll
        for (int i4 = 0; i4 < PCH / 4; ++i4) {
            float4 v = rowp[i4];
            acc = __fadd_rn(acc, v.x);
            acc = __fadd_rn(acc, v.y);
            acc = __fadd_rn(acc, v.z);
            acc = __fadd_rn(acc, v.w);
        }
    }
#undef ISSUE_STAGE

    g_pooled[base + tid] = __fmul_rn(acc, (1.0f / (float)D));
}

// ---------------------------------------------------------------------------
// Kernel B: per batch-item (grid = 32, block = 512), fp32 throughout.
// PROVEN bit-exact (rel_err==0.0). DO NOT MODIFY ARITHMETIC.
// ---------------------------------------------------------------------------
__global__ void __launch_bounds__(512) mlp_sort_kernel(
    const float* __restrict__ W1, const float* __restrict__ b1,
    const float* __restrict__ W2, const float* __restrict__ b2) {
    const int b   = blockIdx.x;
    const int tid = threadIdx.x;

    __shared__ float ps[C];
    __shared__ float hs[H];
    __shared__ float ss[C];
    __shared__ int   si[C];

    ps[tid] = g_pooled[b * C + tid];
    __syncthreads();

    if (tid < H) {
        const float* __restrict__ w = W1 + tid * C;
        float acc = 0.f;
        for (int k = 0; k < C; k++) acc = fmaf(w[k], ps[k], acc);
        acc = __fadd_rn(acc, b1[tid]);
        hs[tid] = (acc >= 0.f) ? acc : __fmul_rn(0.01f, acc);
    }
    __syncthreads();

    {
        const float* __restrict__ w = W2 + tid * H;
        float acc = 0.f;
        for (int k = 0; k < H; k++) acc = fmaf(w[k], hs[k], acc);
        acc = __fadd_rn(acc, b2[tid]);
        float e = xla_cpu_expf(-acc);
        ss[tid] = __fdiv_rn(1.0f, __fadd_rn(1.0f, e));
        si[tid] = tid;
    }
    __syncthreads();

    // Bitonic sort, 512 elems, key = (score desc, idx asc).
    for (int k = 2; k <= C; k <<= 1) {
        for (int j = k >> 1; j > 0; j >>= 1) {
            const int i   = tid;
            const int ixj = i ^ j;
            if (ixj > i) {
                const float a_s = ss[i],  b_s = ss[ixj];
                const int   a_i = si[i],  b_i = si[ixj];
                const bool b_precedes_a = (b_s > a_s) || (b_s == a_s && b_i < a_i);
                const bool a_precedes_b = (a_s > b_s) || (a_s == b_s && a_i < b_i);
                const bool up = ((i & k) == 0);
                const bool do_swap = up ? b_precedes_a : a_precedes_b;
                if (do_swap) {
                    ss[i] = b_s; ss[ixj] = a_s;
                    si[i] = b_i; si[ixj] = a_i;
                }
            }
            __syncthreads();
        }
    }

    g_ord[b * C + tid] = si[tid];
}

// ---------------------------------------------------------------------------
// Kernel C: out[b,c,:] = x[b,c,:] + x[b, ord[b][c], :]
// b-major grid: concurrent blocks share one 8 MiB batch slice (<< 126 MB L2)
// so the gathered second read hits L2, not DRAM.
// ---------------------------------------------------------------------------
__global__ void __launch_bounds__(256) shuffle_add_kernel(
    const float* __restrict__ x, float* __restrict__ out) {
    const int row = blockIdx.x;          // b*512 + c
    const int b   = row >> 9;
    const int src = g_ord[row];

    const float4* __restrict__ xa =
        reinterpret_cast<const float4*>(x + (size_t)row * D);
    const float4* __restrict__ xb =
        reinterpret_cast<const float4*>(x + ((size_t)(b << 9) + src) * D);
    float4* __restrict__ o = reinterpret_cast<float4*>(out + (size_t)row * D);

#pragma unroll 4
    for (int i = threadIdx.x; i < D / 4; i += 256) {
        float4 a = xa[i];
        float4 g = xb[i];
        a.x += g.x; a.y += g.y; a.z += g.z; a.w += g.w;
        o[i] = a;
    }
}

// ---------------------------------------------------------------------------
extern "C" void kernel_launch(void* const* d_in, const int* in_sizes, int n_in,
                              void* d_out, int out_size) {
    const float* x  = (const float*)d_in[0];
    const float* W1 = (const float*)d_in[1];
    const float* b1 = (const float*)d_in[2];
    const float* W2 = (const float*)d_in[3];
    const float* b2 = (const float*)d_in[4];
    float* out = (float*)d_out;

    pool_kernel<<<NROWS / PR, PR>>>(x);
    mlp_sort_kernel<<<B, 512>>>(W1, b1, W2, b2);
    shuffle_add_kernel<<<NROWS, 256>>>(x, out);
}

// round 12
// speedup vs baseline: 2.3229x; 1.0355x over previous
#include <cuda_runtime.h>
#include <math.h>
#include <stdint.h>

// Problem shapes (fixed by the dataset)
#define B  32
#define C  512
#define D  4096
#define H  128        // hidden
#define NROWS (B * C) // 16384

// Pool kernel: warp-private cp.async pipelines
#define PR      128          // rows per block == threads per block (4 warps)
#define PCH     16           // columns per chunk
#define NCH     (D / PCH)    // 256 chunks
#define NSTAGE  4            // smem ring depth (power of 2)
#define SSTRIDE 20           // floats per row slot (16 + 4 pad; 80B, 16B-aligned)

// Scratch (no cudaMalloc allowed)
__device__ float g_pooled[B * C];
__device__ int   g_ord[B * C];

// ---------------------------------------------------------------------------
// Bit-faithful XLA-CPU vectorized expf. PROVEN: rel_err == 0.0. DO NOT MODIFY.
// ---------------------------------------------------------------------------
__device__ __forceinline__ float xla_cpu_expf(float x) {
    const float exp_hi = 88.3762626647950f;
    const float exp_lo = -88.3762626647949f;
    const float LOG2EF = 1.44269504088896341f;
    const float C1 = 0.693359375f;
    const float C2 = -2.12194440e-4f;
    const float p0 = 1.9875691500e-4f;
    const float p1 = 1.3981999507e-3f;
    const float p2 = 8.3334519073e-3f;
    const float p3 = 4.1665795894e-2f;
    const float p4 = 1.6666665459e-1f;
    const float p5 = 5.0000001201e-1f;

    x = fminf(fmaxf(x, exp_lo), exp_hi);

    float fx = __fadd_rn(__fmul_rn(x, LOG2EF), 0.5f);
    fx = floorf(fx);

    float tmp = __fmul_rn(fx, C1);
    float z   = __fmul_rn(fx, C2);
    x = __fsub_rn(x, tmp);
    x = __fsub_rn(x, z);
    z = __fmul_rn(x, x);

    float y = p0;
    y = __fadd_rn(__fmul_rn(y, x), p1);
    y = __fadd_rn(__fmul_rn(y, x), p2);
    y = __fadd_rn(__fmul_rn(y, x), p3);
    y = __fadd_rn(__fmul_rn(y, x), p4);
    y = __fadd_rn(__fmul_rn(y, x), p5);
    y = __fadd_rn(__fmul_rn(y, z), x);
    y = __fadd_rn(y, 1.0f);

    int n = (int)fx;
    y = __fmul_rn(y, __int_as_float((n + 127) << 23));
    return y;
}

// ---------------------------------------------------------------------------
// Kernel A: pooled[row] = (strict sequential fp32 sum over d) * (1/4096).
// IDENTICAL addition order to round 8 (bit-exact). Scheduling: per-WARP
// cp.async pipelines — warp w copies exactly rows [32w, 32w+32) that its own
// lanes consume, so chunk handoff needs only cp.async.wait_group + syncwarp
// (cp.async groups are per-thread; producers and consumers share a warp).
// No __syncthreads in the main loop; warps run fully decoupled.
// Slot algebra: issue 0..2 up front; each iter waits<=2 (chunk ch resident),
// refills slot (ch+3)&3 (distinct from consume slot ch&3); the syncwarp at
// iter ch+1 fences all lanes' chunk-ch reads before slot reuse at ch+4.
// ---------------------------------------------------------------------------
__global__ void __launch_bounds__(PR) pool_kernel(const float* __restrict__ x) {
    __shared__ float ring[NSTAGE][PR * SSTRIDE];   // 4 * 128*20*4B = 40 KB

    const int tid  = threadIdx.x;
    const int wid  = tid >> 5;            // warp id (0..3)
    const int lane = tid & 31;
    const int base = blockIdx.x * PR;
    const int wrow = wid << 5;            // first row of this warp's band
    const float4* __restrict__ x4 = reinterpret_cast<const float4*>(x);

    // Per-warp stage issue: 32 rows x 4 float4 = 128 copies, 4 per lane.
    // g = lane + it*32: r_local = g>>2 (0..31), c4 = g&3.
    // Coalescing: 4 consecutive lanes cover one 64B row segment.
#define ISSUE_STAGE(CH)                                                        \
    do {                                                                       \
        const int _s = (CH) & (NSTAGE - 1);                                    \
        _Pragma("unroll")                                                      \
        for (int _it = 0; _it < 4; ++_it) {                                    \
            const int _g  = lane + _it * 32;                                   \
            const int _r  = wrow + (_g >> 2);                                  \
            const int _c4 = _g & 3;                                            \
            const float4* _src = &x4[(size_t)(base + _r) * (D / 4)             \
                                     + (size_t)(CH) * (PCH / 4) + _c4];        \
            uint32_t _dst = (uint32_t)__cvta_generic_to_shared(                \
                &ring[_s][_r * SSTRIDE + _c4 * 4]);                            \
            asm volatile("cp.async.cg.shared.global [%0], [%1], 16;"           \
                         :: "r"(_dst), "l"(_src) : "memory");                  \
        }                                                                      \
        asm volatile("cp.async.commit_group;" ::: "memory");                   \
    } while (0)

    ISSUE_STAGE(0);
    ISSUE_STAGE(1);
    ISSUE_STAGE(2);

    float acc = 0.f;
    for (int ch = 0; ch < NCH; ++ch) {
        asm volatile("cp.async.wait_group 2;" ::: "memory");
        __syncwarp();      // producers == this warp's lanes: make their
                           // cp.async writes visible; fence prior reads.

        // Refill first (overlaps the add chain below).
        if (ch + 3 < NCH) {
            ISSUE_STAGE(ch + 3);
        } else {
            asm volatile("cp.async.commit_group;" ::: "memory"); // empty group
        }

        // Strict sequential accumulation over this chunk's 16 columns.
        const int s = ch & (NSTAGE - 1);
        const float4* rowp =
            reinterpret_cast<const float4*>(&ring[s][tid * SSTRIDE]);
#pragma unroll
        for (int i4 = 0; i4 < PCH / 4; ++i4) {
            float4 v = rowp[i4];
            acc = __fadd_rn(acc, v.x);
            acc = __fadd_rn(acc, v.y);
            acc = __fadd_rn(acc, v.z);
            acc = __fadd_rn(acc, v.w);
        }
    }
#undef ISSUE_STAGE

    g_pooled[base + tid] = __fmul_rn(acc, (1.0f / (float)D));
}

// ---------------------------------------------------------------------------
// Kernel B: per batch-item (grid = 32, block = 512), fp32 throughout.
// PROVEN bit-exact (rel_err==0.0). DO NOT MODIFY ARITHMETIC.
// ---------------------------------------------------------------------------
__global__ void __launch_bounds__(512) mlp_sort_kernel(
    const float* __restrict__ W1, const float* __restrict__ b1,
    const float* __restrict__ W2, const float* __restrict__ b2) {
    const int b   = blockIdx.x;
    const int tid = threadIdx.x;

    __shared__ float ps[C];
    __shared__ float hs[H];
    __shared__ float ss[C];
    __shared__ int   si[C];

    ps[tid] = g_pooled[b * C + tid];
    __syncthreads();

    if (tid < H) {
        const float* __restrict__ w = W1 + tid * C;
        float acc = 0.f;
        for (int k = 0; k < C; k++) acc = fmaf(w[k], ps[k], acc);
        acc = __fadd_rn(acc, b1[tid]);
        hs[tid] = (acc >= 0.f) ? acc : __fmul_rn(0.01f, acc);
    }
    __syncthreads();

    {
        const float* __restrict__ w = W2 + tid * H;
        float acc = 0.f;
        for (int k = 0; k < H; k++) acc = fmaf(w[k], hs[k], acc);
        acc = __fadd_rn(acc, b2[tid]);
        float e = xla_cpu_expf(-acc);
        ss[tid] = __fdiv_rn(1.0f, __fadd_rn(1.0f, e));
        si[tid] = tid;
    }
    __syncthreads();

    // Bitonic sort, 512 elems, key = (score desc, idx asc).
    for (int k = 2; k <= C; k <<= 1) {
        for (int j = k >> 1; j > 0; j >>= 1) {
            const int i   = tid;
            const int ixj = i ^ j;
            if (ixj > i) {
                const float a_s = ss[i],  b_s = ss[ixj];
                const int   a_i = si[i],  b_i = si[ixj];
                const bool b_precedes_a = (b_s > a_s) || (b_s == a_s && b_i < a_i);
                const bool a_precedes_b = (a_s > b_s) || (a_s == b_s && a_i < b_i);
                const bool up = ((i & k) == 0);
                const bool do_swap = up ? b_precedes_a : a_precedes_b;
                if (do_swap) {
                    ss[i] = b_s; ss[ixj] = a_s;
                    si[i] = b_i; si[ixj] = a_i;
                }
            }
            __syncthreads();
        }
    }

    g_ord[b * C + tid] = si[tid];
}

// ---------------------------------------------------------------------------
// Kernel C: out[b,c,:] = x[b,c,:] + x[b, ord[b][c], :]
// b-major grid -> gathered read re-hits L2 (8 MiB/batch << 126 MB).
// All 8 loads issued before any arithmetic (8 outstanding LDG.128/thread);
// streaming stores (__stcs) keep out from evicting x slices in L2.
// ---------------------------------------------------------------------------
__global__ void __launch_bounds__(256) shuffle_add_kernel(
    const float* __restrict__ x, float* __restrict__ out) {
    const int row = blockIdx.x;          // b*512 + c
    const int b   = row >> 9;
    const int src = g_ord[row];

    const float4* __restrict__ xa =
        reinterpret_cast<const float4*>(x + (size_t)row * D);
    const float4* __restrict__ xb =
        reinterpret_cast<const float4*>(x + ((size_t)(b << 9) + src) * D);
    float4* __restrict__ o = reinterpret_cast<float4*>(out + (size_t)row * D);

    const int t = threadIdx.x;
    float4 a[4], g[4];
#pragma unroll
    for (int i = 0; i < 4; ++i) a[i] = xa[t + i * 256];
#pragma unroll
    for (int i = 0; i < 4; ++i) g[i] = xb[t + i * 256];
#pragma unroll
    for (int i = 0; i < 4; ++i) {
        float4 r;
        r.x = a[i].x + g[i].x;
        r.y = a[i].y + g[i].y;
        r.z = a[i].z + g[i].z;
        r.w = a[i].w + g[i].w;
        __stcs(&o[t + i * 256], r);
    }
}

// ---------------------------------------------------------------------------
extern "C" void kernel_launch(void* const* d_in, const int* in_sizes, int n_in,
                              void* d_out, int out_size) {
    const float* x  = (const float*)d_in[0];
    const float* W1 = (const float*)d_in[1];
    const float* b1 = (const float*)d_in[2];
    const float* W2 = (const float*)d_in[3];
    const float* b2 = (const float*)d_in[4];
    float* out = (float*)d_out;

    pool_kernel<<<NROWS / PR, PR>>>(x);
    mlp_sort_kernel<<<B, 512>>>(W1, b1, W2, b2);
    shuffle_add_kernel<<<NROWS, 256>>>(x, out);
}